// round 16
// baseline (speedup 1.0000x reference)
#include <cuda_runtime.h>
#include <cuda_bf16.h>
#include <cuda_fp16.h>
#include <cstdint>

#define B_ROWS 16384
#define F_DIM  512
#define H_DIM  256
#define E_NUM  8
#define OUT_DIM 32
#define DA     8
#define TM     128
#define NTILES (B_ROWS / TM)   // 128

#define ASTR 36    // b32 stride, 64-fp16 rows (32 words + 4 pad)
#define HSTR 132   // b32 stride, 256-fp16 h rows (128 words + 4 pad)

// ---------------- device scratch ----------------
__device__ int g_counts[E_NUM];
__device__ int g_bucket[E_NUM][B_ROWS];

__device__ __align__(16) __half g_W1T_h[E_NUM][H_DIM][F_DIM];
__device__ __align__(16) __half g_W2T_h[E_NUM][H_DIM][H_DIM];
__device__ __align__(16) __half g_W3T_h[E_NUM][OUT_DIM][H_DIM];

__device__ __forceinline__ uint32_t pack_half2(float v0, float v1) {
    __half2 t = __floats2half2_rn(v0, v1);
    return *reinterpret_cast<uint32_t*>(&t);
}
__device__ __forceinline__ uint32_t smem_u32(const void* p) {
    uint32_t a;
    asm("{ .reg .u64 t; cvta.to.shared.u64 t, %1; cvt.u32.u64 %0, t; }" : "=r"(a) : "l"(p));
    return a;
}
__device__ __forceinline__ void cpasync16(uint32_t dst, const void* src) {
    asm volatile("cp.async.cg.shared.global [%0], [%1], 16;" :: "r"(dst), "l"(src));
}
#define CP_COMMIT() asm volatile("cp.async.commit_group;")
#define CP_WAIT0()  asm volatile("cp.async.wait_group 0;")

__device__ __forceinline__ void mma_fp16(float* d, const uint32_t* a, const uint32_t* b) {
    asm volatile("mma.sync.aligned.m16n8k16.row.col.f32.f16.f16.f32 "
        "{%0,%1,%2,%3}, {%4,%5,%6,%7}, {%8,%9}, {%0,%1,%2,%3};"
        : "+f"(d[0]), "+f"(d[1]), "+f"(d[2]), "+f"(d[3])
        : "r"(a[0]), "r"(a[1]), "r"(a[2]), "r"(a[3]), "r"(b[0]), "r"(b[1]));
}
__device__ __forceinline__ void ldsm_x4(uint32_t* r, uint32_t addr) {
    asm volatile("ldmatrix.sync.aligned.m8n8.x4.shared.b16 {%0,%1,%2,%3}, [%4];"
        : "=r"(r[0]), "=r"(r[1]), "=r"(r[2]), "=r"(r[3]) : "r"(addr));
}

// Warp-tile (32 rows x 32 cols) over NKS*16 K, fp16 single-pass.
template<int LDA, int LDB, int NKS>
__device__ __forceinline__ void mma_chunk_fp16(
    float acc[2][4][4],
    uint32_t aH, uint32_t bH)
{
    #pragma unroll
    for (int ks = 0; ks < NKS; ks++) {
        uint32_t ah[2][4];
        #pragma unroll
        for (int mi = 0; mi < 2; mi++)
            ldsm_x4(ah[mi], aH + mi * (16 * LDA * 4) + ks * 32);
        #pragma unroll
        for (int p = 0; p < 2; p++) {
            uint32_t bh[4];
            ldsm_x4(bh, bH + p * (16 * LDB * 4) + ks * 32);
            #pragma unroll
            for (int q = 0; q < 2; q++) {
                const int ni = p * 2 + q;
                #pragma unroll
                for (int mi = 0; mi < 2; mi++)
                    mma_fp16(acc[mi][ni], ah[mi], bh + q * 2);
            }
        }
    }
}

// ---------------- prep kernels ----------------
__global__ void scatter_kernel(const int* __restrict__ ma) {
    int i = blockIdx.x * blockDim.x + threadIdx.x;
    if (i < B_ROWS) {
        int e = ma[i];
        int p = atomicAdd(&g_counts[e], 1);
        g_bucket[e][p] = i;
    }
}
// also zeroes g_counts (runs before scatter in stream order)
__global__ void prep_weights(const float* __restrict__ W1,
                             const float* __restrict__ W2,
                             const float* __restrict__ W3) {
    int z = blockIdx.z, e = blockIdx.y;
    if (z == 0 && e == 0 && blockIdx.x == 0 && threadIdx.y == 0 && threadIdx.x < E_NUM)
        g_counts[threadIdx.x] = 0;
    int Kd = (z == 0) ? F_DIM : H_DIM;
    int Nd = (z == 0) ? H_DIM : ((z == 1) ? H_DIM : OUT_DIM);
    int ntn = Nd / 32;
    int tk = (blockIdx.x / ntn) * 32;
    int tn = (blockIdx.x % ntn) * 32;
    if (tk >= Kd) return;
    const float* src = ((z == 0) ? W1 : (z == 1) ? W2 : W3) + (size_t)e * Kd * Nd;
    __shared__ float tile[32][33];
    int tx = threadIdx.x, ty = threadIdx.y;   // 32 x 8
    #pragma unroll
    for (int r = 0; r < 4; r++)
        tile[ty + r * 8][tx] = src[(size_t)(tk + ty + r * 8) * Nd + tn + tx];
    __syncthreads();
    #pragma unroll
    for (int r = 0; r < 4; r++) {
        int n = tn + ty + r * 8, k = tk + tx;
        __half v = __float2half_rn(tile[tx][ty + r * 8]);
        if (z == 0)      g_W1T_h[e][n][k] = v;
        else if (z == 1) g_W2T_h[e][n][k] = v;
        else             g_W3T_h[e][n][k] = v;
    }
}

// ---------------- smem layout (b32 words) ----------------
#define B1_H(b)  ((b) * 9216)            // 256 x ASTR per buf; [0, 18432)
#define A_H(b)   (18432 + (b) * 4608)    // 128 x ASTR per buf; [18432, 27648)
#define OFF_HH   0                       // h fp16: 128 x HSTR = 16896 (aliases B1)
#define B2_H(b)  (27648 + (b) * 9216)    // 256 x ASTR per buf; [27648, 46080) DEDICATED
#define OFF_W3H  46080                   // 8 x HSTR = 1056; [46080, 47136) DEDICATED
#define OFF_IDX  47136
#define OFF_SB1  47264
#define OFF_SB2  47520
#define OFF_SB3  47776
#define SMEM_WORDS 47784     // 191136 bytes (1 CTA/SM)

// ---------------- main MMA kernel: 1024 threads, 4x8 warps ----------------
__global__ __launch_bounds__(1024, 1)
void moe_mma_kernel(const float* __restrict__ features,
                    const float* __restrict__ b1,
                    const float* __restrict__ b2,
                    const float* __restrict__ b3,
                    float* __restrict__ out)
{
    const int e = blockIdx.y;
    const int count = g_counts[e];
    const int row0 = blockIdx.x * TM;
    if (row0 >= count) return;
    const int nrows = min(TM, count - row0);

    extern __shared__ uint32_t sm[];
    const uint32_t sb = smem_u32(sm);
    int*   sIdx = (int*)(sm + OFF_IDX);
    float* sB1  = (float*)(sm + OFF_SB1);
    float* sB2  = (float*)(sm + OFF_SB2);
    float* sB3  = (float*)(sm + OFF_SB3);
    uint32_t* hH = sm + OFF_HH;

    const int t    = threadIdx.x;
    const int wid  = t >> 5;
    const int lane = t & 31;
    const int gid  = lane >> 2;
    const int tig  = lane & 3;
    const int wrow = wid & 3;       // 4 row-warps * 32 rows
    const int wcol = wid >> 2;      // 8 col-warps * 32 cols

    // ldmatrix per-lane byte offsets
    const int l8 = lane & 7, lq = lane >> 3;
    const int laneA_A  = ((l8 + 8 * (lq & 1)) * ASTR)  * 4 + (lq >> 1) * 16;
    const int laneA_H  = ((l8 + 8 * (lq & 1)) * HSTR)  * 4 + (lq >> 1) * 16;
    const int laneB_A  = ((l8 + 8 * (lq >> 1)) * ASTR) * 4 + (lq & 1) * 16;

    if (t < TM) sIdx[t] = g_bucket[e][row0 + min(t, nrows - 1)];
    if (t < H_DIM) {
        sB1[t] = b1[e * H_DIM + t];
        sB2[t] = b2[e * H_DIM + t];
    }
    if (t < DA) sB3[t] = b3[e * OUT_DIM + t];
    __syncthreads();

    // staging roles (1024 threads)
    const int arow = t >> 3, aseg = t & 7;     // A: 128 rows x 8 segs of 8 floats
    const int brow = t >> 2, bq = t & 3;       // B: 256 rows x 4 quarters of 16 halves
    const float* frow = features + (size_t)sIdx[arow] * F_DIM;

    const __half* w1h = &g_W1T_h[e][0][0];
    const __half* w2h = &g_W2T_h[e][0][0];
    const __half* w3h = &g_W3T_h[e][0][0];

    float acc[2][4][4];
    #pragma unroll
    for (int mi = 0; mi < 2; mi++)
        #pragma unroll
        for (int ni = 0; ni < 4; ni++)
            #pragma unroll
            for (int c = 0; c < 4; c++) acc[mi][ni][c] = 0.f;

    auto issueB1 = [&](int kc, int buf) {
        const __half* sh = w1h + (size_t)brow * F_DIM + kc * 64 + bq * 16;
        uint32_t dh = sb + (B1_H(buf) + brow * ASTR + bq * 8) * 4;
        #pragma unroll
        for (int c = 0; c < 2; c++)
            cpasync16(dh + c * 16, sh + c * 8);
        CP_COMMIT();
    };
    auto stageA = [&](const float4* v4, int buf) {
        uint32_t* dH = sm + A_H(buf) + arow * ASTR + aseg * 4;
        dH[0] = pack_half2(v4[0].x, v4[0].y);
        dH[1] = pack_half2(v4[0].z, v4[0].w);
        dH[2] = pack_half2(v4[1].x, v4[1].y);
        dH[3] = pack_half2(v4[1].z, v4[1].w);
    };
    // layer-2 chunks are K=64: 64 halves/row, 16 per quarter
    auto issueB2 = [&](int kc, int buf) {
        const __half* sh = w2h + (size_t)brow * H_DIM + kc * 64 + bq * 16;
        uint32_t dh = sb + (B2_H(buf) + brow * ASTR + bq * 8) * 4;
        #pragma unroll
        for (int c = 0; c < 2; c++)
            cpasync16(dh + c * 16, sh + c * 8);
        CP_COMMIT();
    };

    // ============ Layer 1 pipeline: 8 chunks of K=64 (fp16) ============
    {
        issueB1(0, 0);
        {
            float4 v4[2];
            const float* src = frow + aseg * 8;
            v4[0] = *(const float4*)(src);
            v4[1] = *(const float4*)(src + 4);
            stageA(v4, 0);
        }
        #pragma unroll 1
        for (int kc = 0; kc < 8; kc++) {
            const int cur = kc & 1, nxt = cur ^ 1;
            CP_WAIT0();
            __syncthreads();
            float4 v4[2];
            if (kc < 7) {
                issueB1(kc + 1, nxt);
                const float* src = frow + (kc + 1) * 64 + aseg * 8;
                v4[0] = *(const float4*)(src);
                v4[1] = *(const float4*)(src + 4);
            }
            mma_chunk_fp16<ASTR, ASTR, 4>(acc,
                sb + (A_H(cur) + wrow * 32 * ASTR) * 4 + laneA_A,
                sb + (B1_H(cur) + wcol * 32 * ASTR) * 4 + laneB_A);
            if (kc < 7) stageA(v4, nxt);
        }
    }
    __syncthreads();   // layer-1 MMA done: safe to write h (aliases B1)

    issueB2(0, 0);     // layer-2 prologue overlaps epilogue 1 (B2 region dedicated)

    // stage W3T rows 0..7 early (dedicated region; LDG hides under layer-2 pipeline)
    if (t >= 512 && t < 576) {
        int q = t - 512;
        int n = q >> 3, i = (q & 7) * 16;
        const uint4* sh = (const uint4*)(w3h + (size_t)n * H_DIM + i * 2);
        #pragma unroll
        for (int j = 0; j < 4; j++)
            *(uint4*)&sm[OFF_W3H + n * HSTR + i + j * 4] = sh[j];
    }

    // epilogue 1: relu + bias -> h (fp16)
    #pragma unroll
    for (int mi = 0; mi < 2; mi++) {
        int r0 = wrow * 32 + mi * 16 + gid;
        #pragma unroll
        for (int ni = 0; ni < 4; ni++) {
            int col = wcol * 32 + ni * 8 + 2 * tig;
            int cp  = col >> 1;
            float v0 = fmaxf(acc[mi][ni][0] + sB1[col], 0.f);
            float v1 = fmaxf(acc[mi][ni][1] + sB1[col + 1], 0.f);
            float v2 = fmaxf(acc[mi][ni][2] + sB1[col], 0.f);
            float v3 = fmaxf(acc[mi][ni][3] + sB1[col + 1], 0.f);
            hH[r0 * HSTR + cp]       = pack_half2(v0, v1);
            hH[(r0 + 8) * HSTR + cp] = pack_half2(v2, v3);
            acc[mi][ni][0] = 0.f; acc[mi][ni][1] = 0.f;
            acc[mi][ni][2] = 0.f; acc[mi][ni][3] = 0.f;
        }
    }

    // ============ Layer 2 pipeline: 4 chunks of K=64 (fp16) ============
    #pragma unroll 1
    for (int kc = 0; kc < 4; kc++) {
        const int cur = kc & 1, nxt = cur ^ 1;
        CP_WAIT0();
        __syncthreads();   // kc==0: also publishes h + W3 writes
        if (kc < 3) issueB2(kc + 1, nxt);
        mma_chunk_fp16<HSTR, ASTR, 4>(acc,
            sb + (OFF_HH + wrow * 32 * HSTR + kc * 32) * 4 + laneA_H,
            sb + (B2_H(cur) + wcol * 32 * ASTR) * 4 + laneB_A);
    }
    __syncthreads();   // layer-2 MMA done: safe to overwrite h

    // epilogue 2: relu + bias -> h (fp16, overwrite)
    #pragma unroll
    for (int mi = 0; mi < 2; mi++) {
        int r0 = wrow * 32 + mi * 16 + gid;
        #pragma unroll
        for (int ni = 0; ni < 4; ni++) {
            int col = wcol * 32 + ni * 8 + 2 * tig;
            int cp  = col >> 1;
            float v0 = fmaxf(acc[mi][ni][0] + sB2[col], 0.f);
            float v1 = fmaxf(acc[mi][ni][1] + sB2[col + 1], 0.f);
            float v2 = fmaxf(acc[mi][ni][2] + sB2[col], 0.f);
            float v3 = fmaxf(acc[mi][ni][3] + sB2[col + 1], 0.f);
            hH[r0 * HSTR + cp]       = pack_half2(v0, v1);
            hH[(r0 + 8) * HSTR + cp] = pack_half2(v2, v3);
        }
    }
    __syncthreads();

    // ============ Layer 3: y = h2 @ W3[:, :8] + b3 (fp16, warps 0..7) ============
    if (wid < 8) {
        float acc3[4] = {0.f, 0.f, 0.f, 0.f};
        const uint32_t* pAh = hH + wid * 16 * HSTR;
        const uint32_t* w3H = sm + OFF_W3H;
        #pragma unroll
        for (int ks = 0; ks < 16; ks++) {
            const int kb = ks * 8 + tig;
            uint32_t ah[4];
            ah[0] = pAh[gid * HSTR + kb];       ah[1] = pAh[(gid + 8) * HSTR + kb];
            ah[2] = pAh[gid * HSTR + kb + 4];   ah[3] = pAh[(gid + 8) * HSTR + kb + 4];
            uint32_t bh[2] = { w3H[gid * HSTR + kb], w3H[gid * HSTR + kb + 4] };
            mma_fp16(acc3, ah, bh);
        }
        int r0 = wid * 16 + gid;
        int c  = 2 * tig;
        if (r0 < nrows) {
            float* o = out + (size_t)sIdx[r0] * DA + c;
            o[0] = acc3[0] + sB3[c];
            o[1] = acc3[1] + sB3[c + 1];
        }
        if (r0 + 8 < nrows) {
            float* o = out + (size_t)sIdx[r0 + 8] * DA + c;
            o[0] = acc3[2] + sB3[c];
            o[1] = acc3[3] + sB3[c + 1];
        }
    }
}

extern "C" void kernel_launch(void* const* d_in, const int* in_sizes, int n_in,
                              void* d_out, int out_size)
{
    const float* features = (const float*)d_in[0];
    const float* W1 = (const float*)d_in[1];
    const float* b1 = (const float*)d_in[2];
    const float* W2 = (const float*)d_in[3];
    const float* b2 = (const float*)d_in[4];
    const float* W3 = (const float*)d_in[5];
    const float* b3 = (const float*)d_in[6];
    const int*   ma = (const int*)d_in[7];
    float* out = (float*)d_out;

    cudaFuncSetAttribute(moe_mma_kernel, cudaFuncAttributeMaxDynamicSharedMemorySize,
                         SMEM_WORDS * 4);

    prep_weights<<<dim3(128, E_NUM, 3), dim3(32, 8)>>>(W1, W2, W3);  // also zeroes counts
    scatter_kernel<<<B_ROWS / 256, 256>>>(ma);
    moe_mma_kernel<<<dim3(NTILES, E_NUM), 1024, SMEM_WORDS * 4>>>(features, b1, b2, b3, out);
}

// round 17
// speedup vs baseline: 1.0085x; 1.0085x over previous
#include <cuda_runtime.h>
#include <cuda_bf16.h>
#include <cuda_fp16.h>
#include <cstdint>

#define B_ROWS 16384
#define F_DIM  512
#define H_DIM  256
#define E_NUM  8
#define OUT_DIM 32
#define DA     8
#define TM     128
#define NTILES (B_ROWS / TM)   // 128

#define ASTR 36    // b32 stride, 64-fp16 rows (32 words + 4 pad)
#define HSTR 132   // b32 stride, 256-fp16 h rows (128 words + 4 pad)

// ---------------- device scratch ----------------
__device__ int g_counts[E_NUM];
__device__ int g_bucket[E_NUM][B_ROWS];

__device__ __align__(16) __half g_W1T_h[E_NUM][H_DIM][F_DIM];
__device__ __align__(16) __half g_W2T_h[E_NUM][H_DIM][H_DIM];
__device__ __align__(16) __half g_W3T_h[E_NUM][OUT_DIM][H_DIM];

__device__ __forceinline__ uint32_t pack_half2(float v0, float v1) {
    __half2 t = __floats2half2_rn(v0, v1);
    return *reinterpret_cast<uint32_t*>(&t);
}
__device__ __forceinline__ uint32_t smem_u32(const void* p) {
    uint32_t a;
    asm("{ .reg .u64 t; cvta.to.shared.u64 t, %1; cvt.u32.u64 %0, t; }" : "=r"(a) : "l"(p));
    return a;
}
__device__ __forceinline__ void cpasync16(uint32_t dst, const void* src) {
    asm volatile("cp.async.cg.shared.global [%0], [%1], 16;" :: "r"(dst), "l"(src));
}
#define CP_COMMIT() asm volatile("cp.async.commit_group;")
#define CP_WAIT0()  asm volatile("cp.async.wait_group 0;")

__device__ __forceinline__ void mma_fp16(float* d, const uint32_t* a, const uint32_t* b) {
    asm volatile("mma.sync.aligned.m16n8k16.row.col.f32.f16.f16.f32 "
        "{%0,%1,%2,%3}, {%4,%5,%6,%7}, {%8,%9}, {%0,%1,%2,%3};"
        : "+f"(d[0]), "+f"(d[1]), "+f"(d[2]), "+f"(d[3])
        : "r"(a[0]), "r"(a[1]), "r"(a[2]), "r"(a[3]), "r"(b[0]), "r"(b[1]));
}
__device__ __forceinline__ void ldsm_x4(uint32_t* r, uint32_t addr) {
    asm volatile("ldmatrix.sync.aligned.m8n8.x4.shared.b16 {%0,%1,%2,%3}, [%4];"
        : "=r"(r[0]), "=r"(r[1]), "=r"(r[2]), "=r"(r[3]) : "r"(addr));
}

// Warp-tile (32 rows x 64 cols) over NKS*16 K, fp16 single-pass.
// Per k16: 2 A-ldsm + 4 B-ldsm, 16 MMAs (0.375 ldsm/mma).
template<int LDA, int LDB, int NKS>
__device__ __forceinline__ void mma_chunk_fp16(
    float acc[2][8][4],
    uint32_t aH, uint32_t bH)
{
    #pragma unroll
    for (int ks = 0; ks < NKS; ks++) {
        uint32_t ah[2][4];
        #pragma unroll
        for (int mi = 0; mi < 2; mi++)
            ldsm_x4(ah[mi], aH + mi * (16 * LDA * 4) + ks * 32);
        #pragma unroll
        for (int p = 0; p < 4; p++) {
            uint32_t bh[4];
            ldsm_x4(bh, bH + p * (16 * LDB * 4) + ks * 32);
            #pragma unroll
            for (int q = 0; q < 2; q++) {
                const int ni = p * 2 + q;
                #pragma unroll
                for (int mi = 0; mi < 2; mi++)
                    mma_fp16(acc[mi][ni], ah[mi], bh + q * 2);
            }
        }
    }
}

// ---------------- prep kernels ----------------
__global__ void scatter_kernel(const int* __restrict__ ma) {
    int i = blockIdx.x * blockDim.x + threadIdx.x;
    if (i < B_ROWS) {
        int e = ma[i];
        int p = atomicAdd(&g_counts[e], 1);
        g_bucket[e][p] = i;
    }
}
// also zeroes g_counts (runs before scatter in stream order)
__global__ void prep_weights(const float* __restrict__ W1,
                             const float* __restrict__ W2,
                             const float* __restrict__ W3) {
    int z = blockIdx.z, e = blockIdx.y;
    if (z == 0 && e == 0 && blockIdx.x == 0 && threadIdx.y == 0 && threadIdx.x < E_NUM)
        g_counts[threadIdx.x] = 0;
    int Kd = (z == 0) ? F_DIM : H_DIM;
    int Nd = (z == 0) ? H_DIM : ((z == 1) ? H_DIM : OUT_DIM);
    int ntn = Nd / 32;
    int tk = (blockIdx.x / ntn) * 32;
    int tn = (blockIdx.x % ntn) * 32;
    if (tk >= Kd) return;
    const float* src = ((z == 0) ? W1 : (z == 1) ? W2 : W3) + (size_t)e * Kd * Nd;
    __shared__ float tile[32][33];
    int tx = threadIdx.x, ty = threadIdx.y;   // 32 x 8
    #pragma unroll
    for (int r = 0; r < 4; r++)
        tile[ty + r * 8][tx] = src[(size_t)(tk + ty + r * 8) * Nd + tn + tx];
    __syncthreads();
    #pragma unroll
    for (int r = 0; r < 4; r++) {
        int n = tn + ty + r * 8, k = tk + tx;
        __half v = __float2half_rn(tile[tx][ty + r * 8]);
        if (z == 0)      g_W1T_h[e][n][k] = v;
        else if (z == 1) g_W2T_h[e][n][k] = v;
        else             g_W3T_h[e][n][k] = v;
    }
}

// ---------------- smem layout (b32 words) ----------------
#define B1_H(b)  ((b) * 9216)            // 256 x ASTR per buf; [0, 18432)
#define A_H(b)   (18432 + (b) * 4608)    // 128 x ASTR per buf; [18432, 27648)
#define OFF_HH   0                       // h fp16: 128 x HSTR = 16896 (aliases B1)
#define B2_H(b)  (27648 + (b) * 9216)    // 256 x ASTR per buf; [27648, 46080) DEDICATED
#define OFF_W3H  46080                   // 8 x HSTR = 1056; [46080, 47136) DEDICATED
#define OFF_IDX  47136
#define OFF_SB1  47264
#define OFF_SB2  47520
#define OFF_SB3  47776
#define SMEM_WORDS 47784     // 191136 bytes (1 CTA/SM)

// ---------------- main MMA kernel: 512 threads, 4x4 warps ----------------
__global__ __launch_bounds__(512, 1)
void moe_mma_kernel(const float* __restrict__ features,
                    const float* __restrict__ b1,
                    const float* __restrict__ b2,
                    const float* __restrict__ b3,
                    float* __restrict__ out)
{
    const int e = blockIdx.y;
    const int count = g_counts[e];
    const int row0 = blockIdx.x * TM;
    if (row0 >= count) return;
    const int nrows = min(TM, count - row0);

    extern __shared__ uint32_t sm[];
    const uint32_t sb = smem_u32(sm);
    int*   sIdx = (int*)(sm + OFF_IDX);
    float* sB1  = (float*)(sm + OFF_SB1);
    float* sB2  = (float*)(sm + OFF_SB2);
    float* sB3  = (float*)(sm + OFF_SB3);
    uint32_t* hH = sm + OFF_HH;

    const int t    = threadIdx.x;
    const int wid  = t >> 5;
    const int lane = t & 31;
    const int gid  = lane >> 2;
    const int tig  = lane & 3;
    const int wrow = wid & 3;       // 4 row-warps * 32 rows
    const int wcol = wid >> 2;      // 4 col-warps * 64 cols

    // ldmatrix per-lane byte offsets
    const int l8 = lane & 7, lq = lane >> 3;
    const int laneA_A  = ((l8 + 8 * (lq & 1)) * ASTR)  * 4 + (lq >> 1) * 16;
    const int laneA_H  = ((l8 + 8 * (lq & 1)) * HSTR)  * 4 + (lq >> 1) * 16;
    const int laneB_A  = ((l8 + 8 * (lq >> 1)) * ASTR) * 4 + (lq & 1) * 16;

    if (t < TM) sIdx[t] = g_bucket[e][row0 + min(t, nrows - 1)];
    if (t < H_DIM) {
        sB1[t] = b1[e * H_DIM + t];
        sB2[t] = b2[e * H_DIM + t];
    }
    if (t < DA) sB3[t] = b3[e * OUT_DIM + t];
    __syncthreads();

    // staging roles (512 threads)
    const int arow = t >> 2, aseg = t & 3;     // A: 128 rows x 4 segs of 16 floats
    const int brow = t >> 1, bhalf = t & 1;    // B: 256 rows x 2 halves of 32 fp16
    const float* frow = features + (size_t)sIdx[arow] * F_DIM;

    const __half* w1h = &g_W1T_h[e][0][0];
    const __half* w2h = &g_W2T_h[e][0][0];
    const __half* w3h = &g_W3T_h[e][0][0];

    float acc[2][8][4];
    #pragma unroll
    for (int mi = 0; mi < 2; mi++)
        #pragma unroll
        for (int ni = 0; ni < 8; ni++)
            #pragma unroll
            for (int c = 0; c < 4; c++) acc[mi][ni][c] = 0.f;

    auto issueB1 = [&](int kc, int buf) {
        const __half* sh = w1h + (size_t)brow * F_DIM + kc * 64 + bhalf * 32;
        uint32_t dh = sb + (B1_H(buf) + brow * ASTR + bhalf * 16) * 4;
        #pragma unroll
        for (int c = 0; c < 4; c++)
            cpasync16(dh + c * 16, sh + c * 8);
        CP_COMMIT();
    };
    auto stageA = [&](const float4* v4, int buf) {
        uint32_t* dH = sm + A_H(buf) + arow * ASTR + aseg * 8;
        #pragma unroll
        for (int j = 0; j < 4; j++) {
            dH[j * 2]     = pack_half2(v4[j].x, v4[j].y);
            dH[j * 2 + 1] = pack_half2(v4[j].z, v4[j].w);
        }
    };
    // layer-2 chunks are K=64
    auto issueB2 = [&](int kc, int buf) {
        const __half* sh = w2h + (size_t)brow * H_DIM + kc * 64 + bhalf * 32;
        uint32_t dh = sb + (B2_H(buf) + brow * ASTR + bhalf * 16) * 4;
        #pragma unroll
        for (int c = 0; c < 4; c++)
            cpasync16(dh + c * 16, sh + c * 8);
        CP_COMMIT();
    };

    // ============ Layer 1 pipeline: 8 chunks of K=64 (fp16) ============
    {
        issueB1(0, 0);
        {
            float4 v4[4];
            const float* src = frow + aseg * 16;
            #pragma unroll
            for (int j = 0; j < 4; j++) v4[j] = *(const float4*)(src + j * 4);
            stageA(v4, 0);
        }
        #pragma unroll 1
        for (int kc = 0; kc < 8; kc++) {
            const int cur = kc & 1, nxt = cur ^ 1;
            CP_WAIT0();
            __syncthreads();
            float4 v4[4];
            if (kc < 7) {
                issueB1(kc + 1, nxt);
                const float* src = frow + (kc + 1) * 64 + aseg * 16;
                #pragma unroll
                for (int j = 0; j < 4; j++) v4[j] = *(const float4*)(src + j * 4);
            }
            mma_chunk_fp16<ASTR, ASTR, 4>(acc,
                sb + (A_H(cur) + wrow * 32 * ASTR) * 4 + laneA_A,
                sb + (B1_H(cur) + wcol * 64 * ASTR) * 4 + laneB_A);
            if (kc < 7) stageA(v4, nxt);
        }
    }
    __syncthreads();   // layer-1 MMA done: safe to write h (aliases B1)

    issueB2(0, 0);     // layer-2 prologue overlaps epilogue 1 (B2 region dedicated)

    // stage W3T rows 0..7 early (dedicated region)
    if (t < 64) {
        int n = t >> 3, i = (t & 7) * 16;
        const uint4* sh = (const uint4*)(w3h + (size_t)n * H_DIM + i * 2);
        #pragma unroll
        for (int j = 0; j < 4; j++)
            *(uint4*)&sm[OFF_W3H + n * HSTR + i + j * 4] = sh[j];
    }

    // epilogue 1: relu + bias -> h (fp16)
    #pragma unroll
    for (int mi = 0; mi < 2; mi++) {
        int r0 = wrow * 32 + mi * 16 + gid;
        #pragma unroll
        for (int ni = 0; ni < 8; ni++) {
            int col = wcol * 64 + ni * 8 + 2 * tig;
            int cp  = col >> 1;
            float v0 = fmaxf(acc[mi][ni][0] + sB1[col], 0.f);
            float v1 = fmaxf(acc[mi][ni][1] + sB1[col + 1], 0.f);
            float v2 = fmaxf(acc[mi][ni][2] + sB1[col], 0.f);
            float v3 = fmaxf(acc[mi][ni][3] + sB1[col + 1], 0.f);
            hH[r0 * HSTR + cp]       = pack_half2(v0, v1);
            hH[(r0 + 8) * HSTR + cp] = pack_half2(v2, v3);
            acc[mi][ni][0] = 0.f; acc[mi][ni][1] = 0.f;
            acc[mi][ni][2] = 0.f; acc[mi][ni][3] = 0.f;
        }
    }

    // ============ Layer 2 pipeline: 4 chunks of K=64 (fp16) ============
    #pragma unroll 1
    for (int kc = 0; kc < 4; kc++) {
        const int cur = kc & 1, nxt = cur ^ 1;
        CP_WAIT0();
        __syncthreads();   // kc==0: also publishes h + W3 writes
        if (kc < 3) issueB2(kc + 1, nxt);
        mma_chunk_fp16<HSTR, ASTR, 4>(acc,
            sb + (OFF_HH + wrow * 32 * HSTR + kc * 32) * 4 + laneA_H,
            sb + (B2_H(cur) + wcol * 64 * ASTR) * 4 + laneB_A);
    }
    __syncthreads();   // layer-2 MMA done: safe to overwrite h

    // epilogue 2: relu + bias -> h (fp16, overwrite)
    #pragma unroll
    for (int mi = 0; mi < 2; mi++) {
        int r0 = wrow * 32 + mi * 16 + gid;
        #pragma unroll
        for (int ni = 0; ni < 8; ni++) {
            int col = wcol * 64 + ni * 8 + 2 * tig;
            int cp  = col >> 1;
            float v0 = fmaxf(acc[mi][ni][0] + sB2[col], 0.f);
            float v1 = fmaxf(acc[mi][ni][1] + sB2[col + 1], 0.f);
            float v2 = fmaxf(acc[mi][ni][2] + sB2[col], 0.f);
            float v3 = fmaxf(acc[mi][ni][3] + sB2[col + 1], 0.f);
            hH[r0 * HSTR + cp]       = pack_half2(v0, v1);
            hH[(r0 + 8) * HSTR + cp] = pack_half2(v2, v3);
        }
    }
    __syncthreads();

    // ============ Layer 3: y = h2 @ W3[:, :8] + b3 (fp16, warps 0..7) ============
    if (wid < 8) {
        float acc3[4] = {0.f, 0.f, 0.f, 0.f};
        const uint32_t* pAh = hH + wid * 16 * HSTR;
        const uint32_t* w3H = sm + OFF_W3H;
        #pragma unroll
        for (int ks = 0; ks < 16; ks++) {
            const int kb = ks * 8 + tig;
            uint32_t ah[4];
            ah[0] = pAh[gid * HSTR + kb];       ah[1] = pAh[(gid + 8) * HSTR + kb];
            ah[2] = pAh[gid * HSTR + kb + 4];   ah[3] = pAh[(gid + 8) * HSTR + kb + 4];
            uint32_t bh[2] = { w3H[gid * HSTR + kb], w3H[gid * HSTR + kb + 4] };
            mma_fp16(acc3, ah, bh);
        }
        int r0 = wid * 16 + gid;
        int c  = 2 * tig;
        if (r0 < nrows) {
            float* o = out + (size_t)sIdx[r0] * DA + c;
            o[0] = acc3[0] + sB3[c];
            o[1] = acc3[1] + sB3[c + 1];
        }
        if (r0 + 8 < nrows) {
            float* o = out + (size_t)sIdx[r0 + 8] * DA + c;
            o[0] = acc3[2] + sB3[c];
            o[1] = acc3[3] + sB3[c + 1];
        }
    }
}

extern "C" void kernel_launch(void* const* d_in, const int* in_sizes, int n_in,
                              void* d_out, int out_size)
{
    const float* features = (const float*)d_in[0];
    const float* W1 = (const float*)d_in[1];
    const float* b1 = (const float*)d_in[2];
    const float* W2 = (const float*)d_in[3];
    const float* b2 = (const float*)d_in[4];
    const float* W3 = (const float*)d_in[5];
    const float* b3 = (const float*)d_in[6];
    const int*   ma = (const int*)d_in[7];
    float* out = (float*)d_out;

    cudaFuncSetAttribute(moe_mma_kernel, cudaFuncAttributeMaxDynamicSharedMemorySize,
                         SMEM_WORDS * 4);

    prep_weights<<<dim3(128, E_NUM, 3), dim3(32, 8)>>>(W1, W2, W3);  // also zeroes counts
    scatter_kernel<<<B_ROWS / 256, 256>>>(ma);
    moe_mma_kernel<<<dim3(NTILES, E_NUM), 512, SMEM_WORDS * 4>>>(features, b1, b2, b3, out);
}